// round 17
// baseline (speedup 1.0000x reference)
#include <cuda_runtime.h>
#include <cuda_bf16.h>

// Chamfer loss (nearest-target-vertex): B=4, N=16384, M=4096, D=3.
// d2[b,n] = p2 + 2 * min_m (0.5*|v|^2 - p.v);  loss[b] = sum_n d2[b,n] / N
//
// EXACT pruned algorithm, warp-autonomous dense window scan:
//   K1: histogram targets+points into 256 x-bins per batch (+ zero out[]).
//   K2: single-block scan -> offsets/cursors; self-zeroes hist (replay-safe).
//   K3: counting-sort scatter into float4 arrays (w = 0.5|v|^2 / |p|^2).
//   K4: warp = 32 consecutive sorted points. Contiguous sorted-target window
//       scanned from gmem with warp-uniform broadcast loads in MLP=8 batches.
//       Per-lane exact bin-edge stop bound + __all_sync; append-only
//       expansion by 8 bins/side. Exact; worst case degenerates to dense.

#define B_ 4
#define N_ 16384
#define M_ 4096
#define NB 256
#define X0f (-5.0f)
#define Hf 0.0390625f              /* 10/256, exact in binary */
#define INVHf 25.6f
#define R0f 0.15625f               /* initial margin: 4 bins */
#define EXPB 8                     /* expansion step: bins per side */

#define HIST_THREADS 256
#define HIST_BLOCKS ((B_ * (M_ + N_)) / HIST_THREADS)   // 320

#define NN_THREADS 256
#define NN_BLOCKS (B_ * N_ / NN_THREADS)                // 256

__device__ float4 g_tgt_sorted[B_][M_];
__device__ float4 g_pt_sorted[B_][N_];
__device__ int    g_hist[2][B_][NB];      // [0]=targets, [1]=points
__device__ int    g_off[B_][NB + 1];      // target bin offsets
__device__ int    g_cur[2][B_][NB];       // scatter cursors

__device__ __forceinline__ int xbin(float x) {
    int j = (int)floorf((x - X0f) * INVHf);
    return min(max(j, 0), NB - 1);
}

// ---- K1: histogram (and zero out) ----
__global__ __launch_bounds__(HIST_THREADS)
void k1_hist(const float* __restrict__ src,
             const float* __restrict__ tgt,
             float* __restrict__ out) {
    if (blockIdx.x == 0 && threadIdx.x < B_) out[threadIdx.x] = 0.0f;
    int idx = blockIdx.x * HIST_THREADS + threadIdx.x;
    if (idx < B_ * M_) {
        int b = idx / M_;
        atomicAdd(&g_hist[0][b][xbin(tgt[(size_t)idx * 3])], 1);
    } else {
        int r = idx - B_ * M_;
        int b = r / N_;
        atomicAdd(&g_hist[1][b][xbin(src[(size_t)r * 3])], 1);
    }
}

// ---- K2: scan 8 (kind,batch) segments; init cursors; zero hist ----
__global__ __launch_bounds__(256)
void k2_scan() {
    int tid  = threadIdx.x;
    int lane = tid & 31, w = tid >> 5;
    __shared__ int wsum[8];
    for (int seg = 0; seg < 8; seg++) {
        int kind = seg >> 2, b = seg & 3;
        int c = g_hist[kind][b][tid];
        int v = c;
#pragma unroll
        for (int off = 1; off < 32; off <<= 1) {
            int t = __shfl_up_sync(0xffffffffu, v, off);
            if (lane >= off) v += t;
        }
        if (lane == 31) wsum[w] = v;
        __syncthreads();
        int base = 0;
#pragma unroll
        for (int k = 0; k < 8; k++) base += (k < w) ? wsum[k] : 0;
        int incl = v + base;
        int excl = incl - c;
        if (kind == 0) {
            g_off[b][tid] = excl;
            if (tid == NB - 1) g_off[b][NB] = incl;
        }
        g_cur[kind][b][tid] = excl;
        g_hist[kind][b][tid] = 0;          // self-reset for next replay
        __syncthreads();
    }
}

// ---- K3: counting-sort scatter ----
__global__ __launch_bounds__(HIST_THREADS)
void k3_scatter(const float* __restrict__ src,
                const float* __restrict__ tgt) {
    int idx = blockIdx.x * HIST_THREADS + threadIdx.x;
    if (idx < B_ * M_) {
        int b = idx / M_;
        float x = tgt[(size_t)idx * 3 + 0];
        float y = tgt[(size_t)idx * 3 + 1];
        float z = tgt[(size_t)idx * 3 + 2];
        int pos = atomicAdd(&g_cur[0][b][xbin(x)], 1);
        g_tgt_sorted[b][pos] = make_float4(x, y, z, 0.5f * (x*x + y*y + z*z));
    } else {
        int r = idx - B_ * M_;
        int b = r / N_;
        float x = src[(size_t)r * 3 + 0];
        float y = src[(size_t)r * 3 + 1];
        float z = src[(size_t)r * 3 + 2];
        int pos = atomicAdd(&g_cur[1][b][xbin(x)], 1);
        g_pt_sorted[b][pos] = make_float4(x, y, z, x*x + y*y + z*z);
    }
}

// Dense scan of contiguous sorted-target range [lo,hi): warp-uniform
// broadcast loads, 8 in flight (MLP=8), two interleaved min chains.
__device__ __forceinline__ void scan_range(const float4* __restrict__ tv,
                                           int lo, int hi,
                                           float nx, float ny, float nz,
                                           float& b0, float& b1) {
    int t = lo;
    for (; t + 8 <= hi; t += 8) {
        float4 v[8];
#pragma unroll
        for (int k = 0; k < 8; k++) v[k] = tv[t + k];
#pragma unroll
        for (int k = 0; k < 8; k++) {
            float sc = fmaf(v[k].z, nz, fmaf(v[k].y, ny, fmaf(v[k].x, nx, v[k].w)));
            if (k & 1) b1 = fminf(b1, sc); else b0 = fminf(b0, sc);
        }
    }
    for (; t < hi; t++) {
        float4 v = tv[t];
        float sc = fmaf(v.z, nz, fmaf(v.y, ny, fmaf(v.x, nx, v.w)));
        b0 = fminf(b0, sc);
    }
}

// ---- K4: warp-autonomous windowed NN ----
__global__ __launch_bounds__(NN_THREADS)
void k4_nn(float* __restrict__ out) {
    const unsigned FULL = 0xffffffffu;
    const int tid  = threadIdx.x;
    const int lane = tid & 31, wid = tid >> 5;
    const int gidx = blockIdx.x * NN_THREADS + tid;
    const int b    = gidx >> 14;            // 16384 points per batch
    const int i    = gidx & (N_ - 1);

    float4 p = g_pt_sorted[b][i];
    const float nx = -p.x, ny = -p.y, nz = -p.z, p2 = p.w;

    // Warp x-span (lanes are 32 consecutive sorted points).
    float xm = p.x, xM = p.x;
#pragma unroll
    for (int off = 16; off > 0; off >>= 1) {
        xm = fminf(xm, __shfl_xor_sync(FULL, xm, off));
        xM = fmaxf(xM, __shfl_xor_sync(FULL, xM, off));
    }

    const int*    boff = g_off[b];
    const float4* tv   = g_tgt_sorted[b];

    int jlo = xbin(xm - R0f);
    int jhi = xbin(xM + R0f);
    int A   = boff[jlo];           // warp-uniform
    int Bv  = boff[jhi + 1];

    float b0 = 1e30f, b1 = 1e30f;
    scan_range(tv, A, Bv, nx, ny, nz, b0, b1);
    float best = fminf(b0, b1);

    // Exact append-only expansion; per-lane bound, warp-uniform control.
    while (true) {
        float dL = (jlo > 0)      ? fmaxf(p.x - (X0f + jlo * Hf), 0.0f)       : 1e15f;
        float dR = (jhi < NB - 1) ? fmaxf((X0f + (jhi + 1) * Hf) - p.x, 0.0f) : 1e15f;
        float bd2 = fmaxf(fmaf(2.0f, best, p2), 0.0f);
        bool done = (bd2 <= dL * dL) && (bd2 <= dR * dR);
        if (__all_sync(FULL, done)) break;

        int njlo = max(jlo - EXPB, 0);
        int njhi = min(jhi + EXPB, NB - 1);
        int nA   = boff[njlo];
        int nB   = boff[njhi + 1];

        b0 = 1e30f; b1 = 1e30f;
        scan_range(tv, nA, A,  nx, ny, nz, b0, b1);   // new left chunk
        scan_range(tv, Bv, nB, nx, ny, nz, b0, b1);   // new right chunk
        best = fminf(best, fminf(b0, b1));

        jlo = njlo; jhi = njhi; A = nA; Bv = nB;
    }

    // Clamped d^2, block reduce (block is within one batch), one atomic.
    float local = fmaxf(fmaf(2.0f, best, p2), 0.0f);
#pragma unroll
    for (int off = 16; off > 0; off >>= 1)
        local += __shfl_down_sync(FULL, local, off);

    __shared__ float warp_sums[NN_THREADS / 32];
    if (lane == 0) warp_sums[wid] = local;
    __syncthreads();
    if (tid == 0) {
        float ssum = 0.0f;
#pragma unroll
        for (int k = 0; k < NN_THREADS / 32; k++)
            ssum += warp_sums[k];
        atomicAdd(&out[b], ssum * (1.0f / N_));
    }
}

extern "C" void kernel_launch(void* const* d_in, const int* in_sizes, int n_in,
                              void* d_out, int out_size) {
    const float* src = (const float*)d_in[0];
    const float* tgt = (const float*)d_in[1];
    if (n_in >= 2 && in_sizes[0] == B_ * M_ * 3 && in_sizes[1] == B_ * N_ * 3) {
        const float* t = src; src = tgt; tgt = t;
    }
    float* out = (float*)d_out;

    k1_hist<<<HIST_BLOCKS, HIST_THREADS>>>(src, tgt, out);
    k2_scan<<<1, 256>>>();
    k3_scatter<<<HIST_BLOCKS, HIST_THREADS>>>(src, tgt);
    k4_nn<<<NN_BLOCKS, NN_THREADS>>>(out);
}